// round 1
// baseline (speedup 1.0000x reference)
#include <cuda_runtime.h>
#include <cuda_bf16.h>

// MrLoRA: out = x @ (W + sum_i coef_i * B_i @ A_i)^T + b
// Strategy: fold all 5 low-rank updates into W_eff (one cheap memory-bound
// kernel), then a single M=8192, N=4096, K=4096 fp32 GEMM.

#define DIN  4096
#define DOUT 4096
#define MTOT 8192   // 4 * 2048

// Scratch for the effective weight (allocation-free rule: __device__ global).
__device__ float g_Weff[(size_t)DOUT * DIN];

// ---------------------------------------------------------------------------
// Fold kernel: W_eff[o][d] = W[o][d] + sum over 31 rank-rows of coefB * A
// grid: (DIN/1024, DOUT/16), block 256. Each thread: 4 consecutive d (float4),
// 16 o-rows (A columns reused from registers across the 16 rows).
// ---------------------------------------------------------------------------
__global__ __launch_bounds__(256) void fold_kernel(
    const float* __restrict__ W,
    const float* __restrict__ A16, const float* __restrict__ B16,
    const float* __restrict__ A8,  const float* __restrict__ B8,
    const float* __restrict__ A4,  const float* __restrict__ B4,
    const float* __restrict__ A2,  const float* __restrict__ B2,
    const float* __restrict__ A1,  const float* __restrict__ B1,
    const float* __restrict__ alphas)
{
    const int tid   = threadIdx.x;
    const int d0    = (blockIdx.x * 256 + tid) * 4;
    const int obase = blockIdx.y * 16;

    __shared__ float sB[16][32];  // [o_local][rank-row j], 31 used

    // rslora scales: 16/sqrt(r) for r = 16, 8, 4, 2, 1
    for (int t = tid; t < 16 * 31; t += 256) {
        int ol = t / 31, j = t % 31;
        int o = obase + ol;
        float v;
        if      (j < 16) v = B16[o * 16 + j]        * alphas[0] * 4.0f;
        else if (j < 24) v = B8 [o * 8 + (j - 16)]  * alphas[1] * 5.656854249492380f;
        else if (j < 28) v = B4 [o * 4 + (j - 24)]  * alphas[2] * 8.0f;
        else if (j < 30) v = B2 [o * 2 + (j - 28)]  * alphas[3] * 11.313708498984761f;
        else             v = B1 [o]                 * alphas[4] * 16.0f;
        sB[ol][j] = v;
    }
    __syncthreads();

    // Load the 31 A-row segments for this thread's 4 d's into registers.
    float4 a[31];
#pragma unroll
    for (int r = 0; r < 16; r++) a[r]      = *(const float4*)(A16 + (size_t)r * DIN + d0);
#pragma unroll
    for (int r = 0; r < 8; r++)  a[16 + r] = *(const float4*)(A8  + (size_t)r * DIN + d0);
#pragma unroll
    for (int r = 0; r < 4; r++)  a[24 + r] = *(const float4*)(A4  + (size_t)r * DIN + d0);
#pragma unroll
    for (int r = 0; r < 2; r++)  a[28 + r] = *(const float4*)(A2  + (size_t)r * DIN + d0);
    a[30] = *(const float4*)(A1 + d0);

#pragma unroll 2
    for (int ol = 0; ol < 16; ol++) {
        int o = obase + ol;
        float4 acc = *(const float4*)(W + (size_t)o * DIN + d0);
#pragma unroll
        for (int j = 0; j < 31; j++) {
            float c = sB[ol][j];
            acc.x = fmaf(c, a[j].x, acc.x);
            acc.y = fmaf(c, a[j].y, acc.y);
            acc.z = fmaf(c, a[j].z, acc.z);
            acc.w = fmaf(c, a[j].w, acc.w);
        }
        *(float4*)(g_Weff + (size_t)o * DIN + d0) = acc;
    }
}

// ---------------------------------------------------------------------------
// GEMM: out[m][n] = sum_k x[m][k] * Weff[n][k] + bias[n]
// 128x128 block tile, BK=8, 256 threads, 8x8 per-thread register tile,
// register prefetch of next global tile.
// ---------------------------------------------------------------------------
#define BM 128
#define BN 128
#define BK 8
#define TM 8
#define TN 8

__global__ __launch_bounds__(256) void gemm_kernel(
    const float* __restrict__ X,
    const float* __restrict__ bias,
    float* __restrict__ out)
{
    const float* Wf = g_Weff;

    __shared__ float sX[BK][BM];
    __shared__ float sW[BK][BN];

    const int tid = threadIdx.x;
    const int m0  = blockIdx.y * BM;
    const int n0  = blockIdx.x * BN;

    // loader mapping: each thread loads one float4 from X tile and one from W tile
    const int lrow = tid >> 1;          // 0..127
    const int lk   = (tid & 1) * 4;     // 0 or 4

    const float* xptr = X  + (size_t)(m0 + lrow) * DIN + lk;
    const float* wptr = Wf + (size_t)(n0 + lrow) * DIN + lk;

    // compute mapping
    const int tx  = tid & 15;   // n dir
    const int ty  = tid >> 4;   // m dir
    const int tm0 = ty * TM;
    const int tn0 = tx * TN;

    float acc[TM][TN];
#pragma unroll
    for (int i = 0; i < TM; i++)
#pragma unroll
        for (int j = 0; j < TN; j++) acc[i][j] = 0.0f;

    // prefetch first tile into registers
    float4 px = *(const float4*)(xptr);
    float4 pw = *(const float4*)(wptr);

    for (int kt = 0; kt < DIN; kt += BK) {
        // stage registers -> smem (transposed: [k][row])
        sX[lk + 0][lrow] = px.x; sX[lk + 1][lrow] = px.y;
        sX[lk + 2][lrow] = px.z; sX[lk + 3][lrow] = px.w;
        sW[lk + 0][lrow] = pw.x; sW[lk + 1][lrow] = pw.y;
        sW[lk + 2][lrow] = pw.z; sW[lk + 3][lrow] = pw.w;
        __syncthreads();

        // prefetch next global tile while computing this one
        if (kt + BK < DIN) {
            px = *(const float4*)(xptr + kt + BK);
            pw = *(const float4*)(wptr + kt + BK);
        }

#pragma unroll
        for (int k = 0; k < BK; k++) {
            float ar[TM], br[TN];
            *(float4*)&ar[0] = *(const float4*)&sX[k][tm0];
            *(float4*)&ar[4] = *(const float4*)&sX[k][tm0 + 4];
            *(float4*)&br[0] = *(const float4*)&sW[k][tn0];
            *(float4*)&br[4] = *(const float4*)&sW[k][tn0 + 4];
#pragma unroll
            for (int i = 0; i < TM; i++)
#pragma unroll
                for (int j = 0; j < TN; j++)
                    acc[i][j] = fmaf(ar[i], br[j], acc[i][j]);
        }
        __syncthreads();
    }

    // epilogue: add bias, vectorized stores
    const float4 bv0 = *(const float4*)(bias + n0 + tn0);
    const float4 bv1 = *(const float4*)(bias + n0 + tn0 + 4);

#pragma unroll
    for (int i = 0; i < TM; i++) {
        const size_t m = (size_t)(m0 + tm0 + i);
        float4 o0, o1;
        o0.x = acc[i][0] + bv0.x; o0.y = acc[i][1] + bv0.y;
        o0.z = acc[i][2] + bv0.z; o0.w = acc[i][3] + bv0.w;
        o1.x = acc[i][4] + bv1.x; o1.y = acc[i][5] + bv1.y;
        o1.z = acc[i][6] + bv1.z; o1.w = acc[i][7] + bv1.w;
        *(float4*)(out + m * DOUT + n0 + tn0)     = o0;
        *(float4*)(out + m * DOUT + n0 + tn0 + 4) = o1;
    }
}

extern "C" void kernel_launch(void* const* d_in, const int* in_sizes, int n_in,
                              void* d_out, int out_size)
{
    const float* x      = (const float*)d_in[0];
    const float* W      = (const float*)d_in[1];
    const float* b      = (const float*)d_in[2];
    const float* A16    = (const float*)d_in[3];
    const float* B16    = (const float*)d_in[4];
    const float* A8     = (const float*)d_in[5];
    const float* B8     = (const float*)d_in[6];
    const float* A4     = (const float*)d_in[7];
    const float* B4     = (const float*)d_in[8];
    const float* A2     = (const float*)d_in[9];
    const float* B2     = (const float*)d_in[10];
    const float* A1     = (const float*)d_in[11];
    const float* B1     = (const float*)d_in[12];
    const float* alphas = (const float*)d_in[13];
    float* out          = (float*)d_out;

    // 1) fold LoRA updates into W_eff
    {
        dim3 grid(DIN / (256 * 4), DOUT / 16);
        fold_kernel<<<grid, 256>>>(W, A16, B16, A8, B8, A4, B4, A2, B2, A1, B1, alphas);
    }

    // 2) single big GEMM + bias
    {
        dim3 grid(DOUT / BN, MTOT / BM);
        gemm_kernel<<<grid, 256>>>(x, b, out);
    }
}

// round 3
// speedup vs baseline: 2.0278x; 2.0278x over previous
#include <cuda_runtime.h>
#include <cuda_bf16.h>
#include <cstdint>

// MrLoRA: out = x @ (W + sum_i coef_i B_i A_i)^T + b
// 1) cvt_x:  x fp32 -> x_hi/x_lo bf16
// 2) fold:   W_eff = W + sum coef*B*A -> w_hi/w_lo bf16
// 3) gemm:   mma.sync bf16 HMMA, fused 3-term split product:
//            out ~= x_hi*w_hi + x_hi*w_lo + x_lo*w_hi  (fp32 accum) + bias
// NOTE: tcgen05 is NOT usable here (harness PTX target is compute_103,
// arch-specific instructions rejected). mma.sync is compute_80-portable.

#define DIN   4096
#define DOUT  4096
#define MTOT  8192

__device__ __nv_bfloat16 g_xhi[(size_t)MTOT * DIN];
__device__ __nv_bfloat16 g_xlo[(size_t)MTOT * DIN];
__device__ __nv_bfloat16 g_whi[(size_t)DOUT * DIN];
__device__ __nv_bfloat16 g_wlo[(size_t)DOUT * DIN];

// ---------------------------------------------------------------------------
// helpers
// ---------------------------------------------------------------------------
__device__ __forceinline__ uint32_t smem_u32(const void* p) {
    uint32_t a;
    asm("{ .reg .u64 t; cvta.to.shared.u64 t, %1; cvt.u32.u64 %0, t; }"
        : "=r"(a) : "l"(p));
    return a;
}
__device__ __forceinline__ void cp16(uint32_t dst, const void* src) {
    asm volatile("cp.async.cg.shared.global [%0], [%1], 16;"
                 :: "r"(dst), "l"(src) : "memory");
}
__device__ __forceinline__ void cp_commit() {
    asm volatile("cp.async.commit_group;" ::: "memory");
}
__device__ __forceinline__ void cp_wait1() {
    asm volatile("cp.async.wait_group 1;" ::: "memory");
}
__device__ __forceinline__ void ldsm_x4(uint32_t& r0, uint32_t& r1,
                                        uint32_t& r2, uint32_t& r3, uint32_t a) {
    asm volatile("ldmatrix.sync.aligned.m8n8.x4.shared.b16 {%0,%1,%2,%3}, [%4];"
                 : "=r"(r0), "=r"(r1), "=r"(r2), "=r"(r3) : "r"(a));
}
__device__ __forceinline__ void mma16816(float* d, const uint32_t* a,
                                         const uint32_t* b) {
    asm volatile(
        "mma.sync.aligned.m16n8k16.row.col.f32.bf16.bf16.f32 "
        "{%0,%1,%2,%3}, {%4,%5,%6,%7}, {%8,%9}, {%0,%1,%2,%3};"
        : "+f"(d[0]), "+f"(d[1]), "+f"(d[2]), "+f"(d[3])
        : "r"(a[0]), "r"(a[1]), "r"(a[2]), "r"(a[3]), "r"(b[0]), "r"(b[1]));
}

// ---------------------------------------------------------------------------
// conversion kernels
// ---------------------------------------------------------------------------
__global__ __launch_bounds__(256) void cvt_x_kernel(const float* __restrict__ x) {
    size_t i = ((size_t)blockIdx.x * 256 + threadIdx.x) * 4;
    float4 v = *(const float4*)(x + i);
    __nv_bfloat16 h0 = __float2bfloat16_rn(v.x);
    __nv_bfloat16 h1 = __float2bfloat16_rn(v.y);
    __nv_bfloat16 h2 = __float2bfloat16_rn(v.z);
    __nv_bfloat16 h3 = __float2bfloat16_rn(v.w);
    __nv_bfloat16 l0 = __float2bfloat16_rn(v.x - __bfloat162float(h0));
    __nv_bfloat16 l1 = __float2bfloat16_rn(v.y - __bfloat162float(h1));
    __nv_bfloat16 l2 = __float2bfloat16_rn(v.z - __bfloat162float(h2));
    __nv_bfloat16 l3 = __float2bfloat16_rn(v.w - __bfloat162float(h3));
    *(__nv_bfloat162*)(g_xhi + i)     = __nv_bfloat162(h0, h1);
    *(__nv_bfloat162*)(g_xhi + i + 2) = __nv_bfloat162(h2, h3);
    *(__nv_bfloat162*)(g_xlo + i)     = __nv_bfloat162(l0, l1);
    *(__nv_bfloat162*)(g_xlo + i + 2) = __nv_bfloat162(l2, l3);
}

__global__ __launch_bounds__(256) void fold_kernel(
    const float* __restrict__ W,
    const float* __restrict__ A16, const float* __restrict__ B16,
    const float* __restrict__ A8,  const float* __restrict__ B8,
    const float* __restrict__ A4,  const float* __restrict__ B4,
    const float* __restrict__ A2,  const float* __restrict__ B2,
    const float* __restrict__ A1,  const float* __restrict__ B1,
    const float* __restrict__ alphas)
{
    const int tid   = threadIdx.x;
    const int d0    = (blockIdx.x * 256 + tid) * 4;
    const int obase = blockIdx.y * 16;

    __shared__ float sB[16][32];
    for (int t = tid; t < 16 * 31; t += 256) {
        int ol = t / 31, j = t % 31;
        int o = obase + ol;
        float v;
        if      (j < 16) v = B16[o * 16 + j]       * alphas[0] * 4.0f;
        else if (j < 24) v = B8 [o * 8 + (j - 16)] * alphas[1] * 5.656854249492380f;
        else if (j < 28) v = B4 [o * 4 + (j - 24)] * alphas[2] * 8.0f;
        else if (j < 30) v = B2 [o * 2 + (j - 28)] * alphas[3] * 11.313708498984761f;
        else             v = B1 [o]                * alphas[4] * 16.0f;
        sB[ol][j] = v;
    }
    __syncthreads();

    float4 a[31];
#pragma unroll
    for (int r = 0; r < 16; r++) a[r]      = *(const float4*)(A16 + (size_t)r * DIN + d0);
#pragma unroll
    for (int r = 0; r < 8; r++)  a[16 + r] = *(const float4*)(A8  + (size_t)r * DIN + d0);
#pragma unroll
    for (int r = 0; r < 4; r++)  a[24 + r] = *(const float4*)(A4  + (size_t)r * DIN + d0);
#pragma unroll
    for (int r = 0; r < 2; r++)  a[28 + r] = *(const float4*)(A2  + (size_t)r * DIN + d0);
    a[30] = *(const float4*)(A1 + d0);

#pragma unroll 2
    for (int ol = 0; ol < 16; ol++) {
        int o = obase + ol;
        float4 acc = *(const float4*)(W + (size_t)o * DIN + d0);
#pragma unroll
        for (int j = 0; j < 31; j++) {
            float c = sB[ol][j];
            acc.x = fmaf(c, a[j].x, acc.x);
            acc.y = fmaf(c, a[j].y, acc.y);
            acc.z = fmaf(c, a[j].z, acc.z);
            acc.w = fmaf(c, a[j].w, acc.w);
        }
        __nv_bfloat16 h0 = __float2bfloat16_rn(acc.x);
        __nv_bfloat16 h1 = __float2bfloat16_rn(acc.y);
        __nv_bfloat16 h2 = __float2bfloat16_rn(acc.z);
        __nv_bfloat16 h3 = __float2bfloat16_rn(acc.w);
        __nv_bfloat16 l0 = __float2bfloat16_rn(acc.x - __bfloat162float(h0));
        __nv_bfloat16 l1 = __float2bfloat16_rn(acc.y - __bfloat162float(h1));
        __nv_bfloat16 l2 = __float2bfloat16_rn(acc.z - __bfloat162float(h2));
        __nv_bfloat16 l3 = __float2bfloat16_rn(acc.w - __bfloat162float(h3));
        size_t off = (size_t)o * DIN + d0;
        *(__nv_bfloat162*)(g_whi + off)     = __nv_bfloat162(h0, h1);
        *(__nv_bfloat162*)(g_whi + off + 2) = __nv_bfloat162(h2, h3);
        *(__nv_bfloat162*)(g_wlo + off)     = __nv_bfloat162(l0, l1);
        *(__nv_bfloat162*)(g_wlo + off + 2) = __nv_bfloat162(l2, l3);
    }
}

// ---------------------------------------------------------------------------
// HMMA GEMM
//   CTA tile: 128(M) x 256(N), BK=32, 3 stages
//   256 threads = 8 warps, warp grid 2(M) x 4(N), warp tile 64x64
//   smem rows padded to 80B (32 bf16 + 16B pad) -> conflict-free ldmatrix
// ---------------------------------------------------------------------------
#define BM      128
#define BN      256
#define BK      32
#define NSTAGE  3
#define PITCH   80
#define OFF_AHI 0
#define OFF_ALO (BM * PITCH)                 // 10240
#define OFF_BHI (2 * BM * PITCH)             // 20480
#define OFF_BLO (2 * BM * PITCH + BN * PITCH) // 40960
#define STAGEB  (2 * BM * PITCH + 2 * BN * PITCH) // 61440
#define NIT     (DIN / BK)                   // 128

__global__ __launch_bounds__(256, 1) void gemm_hmma(
    const float* __restrict__ bias, float* __restrict__ out)
{
    extern __shared__ char smem[];
    const uint32_t sbase = smem_u32(smem);
    const int tid    = threadIdx.x;
    const int wid    = tid >> 5;
    const int lane   = tid & 31;
    const int warp_m = (wid >> 2) * 64;   // 0 or 64
    const int warp_n = (wid & 3) * 64;    // 0,64,128,192
    const int m0     = blockIdx.y * BM;
    const int n0     = blockIdx.x * BN;

    // ---- loader mapping: 768 rows/stage, thread handles rows tid, tid+256, tid+512
    const __nv_bfloat16* srcs[3];
    uint32_t dsts[3];
    {
#pragma unroll
        for (int j = 0; j < 3; j++) {
            int r = tid + j * 256;
            const __nv_bfloat16* s;
            uint32_t o;
            if (r < 128)      { s = g_xhi + (size_t)(m0 + r) * DIN;        o = OFF_AHI + r * PITCH; }
            else if (r < 256) { s = g_xlo + (size_t)(m0 + r - 128) * DIN;  o = OFF_ALO + (r - 128) * PITCH; }
            else if (r < 512) { s = g_whi + (size_t)(n0 + r - 256) * DIN;  o = OFF_BHI + (r - 256) * PITCH; }
            else              { s = g_wlo + (size_t)(n0 + r - 512) * DIN;  o = OFF_BLO + (r - 512) * PITCH; }
            srcs[j] = s;
            dsts[j] = sbase + o;
        }
    }

#define LOAD_STAGE(sidx, kit)                                              \
    do {                                                                   \
        const int kel = (kit) * BK;                                        \
        const uint32_t so = (uint32_t)((sidx) * STAGEB);                   \
        _Pragma("unroll")                                                  \
        for (int j = 0; j < 3; j++) {                                      \
            const __nv_bfloat16* sp = srcs[j] + kel;                       \
            uint32_t dp = dsts[j] + so;                                    \
            cp16(dp,      sp);                                             \
            cp16(dp + 16, sp + 8);                                         \
            cp16(dp + 32, sp + 16);                                        \
            cp16(dp + 48, sp + 24);                                        \
        }                                                                  \
    } while (0)

    // ---- fragment smem addresses (per k16 step q: chunk base q*32 bytes)
    // A: lanes 0-15 -> rows (l&15), lanes 16-31 -> same rows, +16B
    const uint32_t a_row  = warp_m + (lane & 15);
    const uint32_t a_coff = (lane >> 4) * 16;
    // B: n-row = (l&7) + (l>=16 ? 8 : 0); chunk = (l>>3)&1
    const uint32_t b_row  = warp_n + (lane & 7) + ((lane >> 4) << 3);
    const uint32_t b_coff = ((lane >> 3) & 1) * 16;

    float acc[4][8][4];
#pragma unroll
    for (int i = 0; i < 4; i++)
#pragma unroll
        for (int j = 0; j < 8; j++)
#pragma unroll
            for (int q = 0; q < 4; q++) acc[i][j][q] = 0.0f;

    // ---- prologue: stages 0,1
    LOAD_STAGE(0, 0); cp_commit();
    LOAD_STAGE(1, 1); cp_commit();

    for (int it = 0; it < NIT; ++it) {
        cp_wait1();
        __syncthreads();

        const int ps = it + 2;
        if (ps < NIT) LOAD_STAGE(ps % NSTAGE, ps);
        cp_commit();

        const uint32_t sb = sbase + (uint32_t)((it % NSTAGE) * STAGEB);
#pragma unroll
        for (int q = 0; q < 2; q++) {
            const uint32_t kc = q * 32;  // byte offset of k16 within row
            uint32_t aH[4][4], aL[4][4], bH[8][2], bL[8][2];
#pragma unroll
            for (int i = 0; i < 4; i++) {
                uint32_t ad = (a_row + i * 16) * PITCH + kc + a_coff;
                ldsm_x4(aH[i][0], aH[i][1], aH[i][2], aH[i][3],
                        sb + OFF_AHI + ad);
                ldsm_x4(aL[i][0], aL[i][1], aL[i][2], aL[i][3],
                        sb + OFF_ALO + ad);
            }
#pragma unroll
            for (int j = 0; j < 4; j++) {
                uint32_t bd = (b_row + j * 16) * PITCH + kc + b_coff;
                ldsm_x4(bH[2 * j][0], bH[2 * j][1], bH[2 * j + 1][0], bH[2 * j + 1][1],
                        sb + OFF_BHI + bd);
                ldsm_x4(bL[2 * j][0], bL[2 * j][1], bL[2 * j + 1][0], bL[2 * j + 1][1],
                        sb + OFF_BLO + bd);
            }
#pragma unroll
            for (int i = 0; i < 4; i++)
#pragma unroll
                for (int j = 0; j < 8; j++) {
                    mma16816(acc[i][j], aH[i], bH[j]);
                    mma16816(acc[i][j], aH[i], bL[j]);
                    mma16816(acc[i][j], aL[i], bH[j]);
                }
        }
        __syncthreads();
    }

    // ---- epilogue: acc -> gmem with bias
    const int rbase = m0 + warp_m + (lane >> 2);
    const int cbase = n0 + warp_n + (lane & 3) * 2;
#pragma unroll
    for (int j = 0; j < 8; j++) {
        const int c = cbase + j * 8;
        const float2 bv = *(const float2*)(bias + c);
#pragma unroll
        for (int i = 0; i < 4; i++) {
            const int r = rbase + i * 16;
            float2 v0, v1;
            v0.x = acc[i][j][0] + bv.x; v0.y = acc[i][j][1] + bv.y;
            v1.x = acc[i][j][2] + bv.x; v1.y = acc[i][j][3] + bv.y;
            *(float2*)(out + (size_t)r * DOUT + c)       = v0;
            *(float2*)(out + (size_t)(r + 8) * DOUT + c) = v1;
        }
    }
}

// ===========================================================================
extern "C" void kernel_launch(void* const* d_in, const int* in_sizes, int n_in,
                              void* d_out, int out_size)
{
    const float* x      = (const float*)d_in[0];
    const float* W      = (const float*)d_in[1];
    const float* b      = (const float*)d_in[2];
    const float* A16    = (const float*)d_in[3];
    const float* B16    = (const float*)d_in[4];
    const float* A8     = (const float*)d_in[5];
    const float* B8     = (const float*)d_in[6];
    const float* A4     = (const float*)d_in[7];
    const float* B4     = (const float*)d_in[8];
    const float* A2     = (const float*)d_in[9];
    const float* B2     = (const float*)d_in[10];
    const float* A1     = (const float*)d_in[11];
    const float* B1     = (const float*)d_in[12];
    const float* alphas = (const float*)d_in[13];
    float* out          = (float*)d_out;

    cvt_x_kernel<<<(MTOT * DIN) / (256 * 4), 256>>>(x);
    {
        dim3 grid(DIN / (256 * 4), DOUT / 16);
        fold_kernel<<<grid, 256>>>(W, A16, B16, A8, B8, A4, B4, A2, B2, A1, B1, alphas);
    }
    {
        static bool attr_set = false;
        if (!attr_set) {
            cudaFuncSetAttribute(gemm_hmma, cudaFuncAttributeMaxDynamicSharedMemorySize,
                                 NSTAGE * STAGEB);
            attr_set = true;
        }
        dim3 grid(DOUT / BN, MTOT / BM);  // (16, 64)
        gemm_hmma<<<grid, 256, NSTAGE * STAGEB>>>(b, out);
    }
}